// round 1
// baseline (speedup 1.0000x reference)
#include <cuda_runtime.h>
#include <cstdint>

// Problem constants (fixed by the reference)
#define NUM_ROI 148
#define PP      1
#define QQ      5
#define NN      131072

// Each thread handles 4 consecutive n (float4 stores).
// Block = 128 threads -> 512 n per block -> 256 blocks.
#define TPB        128
#define N_PER_THR  4

__global__ __launch_bounds__(TPB) void coconet_kernel(
    const float* __restrict__ X,    // [N, 1]
    const float* __restrict__ Z,    // [N, 5]
    const float* __restrict__ Wr,   // [148, 5]
    const float* __restrict__ br,   // [148]
    const float* __restrict__ Wf,   // [148, 6]
    const float* __restrict__ bf,   // [148]
    float* __restrict__ out)        // [2, 148, N] : r_out then f_out
{
    // Packed per-ROI weights: 4 x float4 per ROI
    //  w0 = {Wf0, Wf1, Wf2, Wf3}
    //  w1 = {Wf4, Wf5, bf,  br }
    //  w2 = {Wr0, Wr1, Wr2, Wr3}
    //  w3 = {Wr4, 0,   0,   0  }
    __shared__ float4 wsh[NUM_ROI][4];

    const int tid = threadIdx.x;

    for (int i = tid; i < NUM_ROI; i += TPB) {
        const float* wf = Wf + i * 6;
        const float* wr = Wr + i * 5;
        wsh[i][0] = make_float4(wf[0], wf[1], wf[2], wf[3]);
        wsh[i][1] = make_float4(wf[4], wf[5], bf[i], br[i]);
        wsh[i][2] = make_float4(wr[0], wr[1], wr[2], wr[3]);
        wsh[i][3] = make_float4(wr[4], 0.f, 0.f, 0.f);
    }
    __syncthreads();

    const int n0 = (blockIdx.x * TPB + tid) * N_PER_THR;

    // Load the 4 rows' inputs once into registers.
    float x[N_PER_THR];
    float z[N_PER_THR][QQ];
#pragma unroll
    for (int j = 0; j < N_PER_THR; ++j) {
        const int n = n0 + j;
        x[j] = __ldg(X + n);
        const float* zp = Z + (size_t)n * QQ;
#pragma unroll
        for (int q = 0; q < QQ; ++q) z[j][q] = __ldg(zp + q);
    }

    float* __restrict__ out_r = out;
    float* __restrict__ out_f = out + (size_t)NUM_ROI * NN;

#pragma unroll 4
    for (int r = 0; r < NUM_ROI; ++r) {
        const float4 a = wsh[r][0];
        const float4 b = wsh[r][1];
        const float4 c = wsh[r][2];
        const float4 d = wsh[r][3];

        float rv[N_PER_THR], fv[N_PER_THR];
#pragma unroll
        for (int j = 0; j < N_PER_THR; ++j) {
            // f_out = bf + Wf[0]*X + Wf[1..5] . Z
            float f = b.z;
            f = fmaf(a.x, x[j],    f);
            f = fmaf(a.y, z[j][0], f);
            f = fmaf(a.z, z[j][1], f);
            f = fmaf(a.w, z[j][2], f);
            f = fmaf(b.x, z[j][3], f);
            f = fmaf(b.y, z[j][4], f);
            fv[j] = f;
            // r_out = br + Wr . Z
            float rr = b.w;
            rr = fmaf(c.x, z[j][0], rr);
            rr = fmaf(c.y, z[j][1], rr);
            rr = fmaf(c.z, z[j][2], rr);
            rr = fmaf(c.w, z[j][3], rr);
            rr = fmaf(d.x, z[j][4], rr);
            rv[j] = rr;
        }

        const size_t off = (size_t)r * NN + n0;
        __stcs(reinterpret_cast<float4*>(out_r + off),
               make_float4(rv[0], rv[1], rv[2], rv[3]));
        __stcs(reinterpret_cast<float4*>(out_f + off),
               make_float4(fv[0], fv[1], fv[2], fv[3]));
    }
}

extern "C" void kernel_launch(void* const* d_in, const int* in_sizes, int n_in,
                              void* d_out, int out_size)
{
    const float* X  = (const float*)d_in[0];
    const float* Z  = (const float*)d_in[1];
    const float* Wr = (const float*)d_in[2];
    const float* br = (const float*)d_in[3];
    const float* Wf = (const float*)d_in[4];
    const float* bf = (const float*)d_in[5];
    float* out = (float*)d_out;

    const int grid = NN / (TPB * N_PER_THR);  // 256
    coconet_kernel<<<grid, TPB>>>(X, Z, Wr, br, Wf, bf, out);
}